// round 8
// baseline (speedup 1.0000x reference)
#include <cuda_runtime.h>
#include <math.h>

#define NE 8
#define NC 1000
#define DFEAT 59
#define NH1 256
#define NH2 128
#define MAXB 16384
#define LN2F 0.69314718055994530942f

// scratch (no allocations allowed)
__device__ float g_h1[(size_t)MAXB * NH1];
__device__ float g_h2[(size_t)MAXB * NH2];

__device__ __forceinline__ float clipf(float x) {
    return fminf(fmaxf(x, -100.0f), 100.0f);
}

__device__ __forceinline__ float warp_sum(float v) {
    #pragma unroll
    for (int o = 16; o; o >>= 1) v += __shfl_xor_sync(0xffffffffu, v, o);
    return v;
}

// ---------------------------------------------------------------------------
// Kernel 1: feature extraction. One block per token (256 threads = 8 warps).
// Logs on MUFU (LG2), accumulate in log2 domain, scale by ln2 at the end.
// ---------------------------------------------------------------------------
__global__ __launch_bounds__(256) void feat_kernel(
    const float* __restrict__ post, float* __restrict__ outFeats)
{
    __shared__ float tile[NE * NC];   // 32 KB
    __shared__ float s_mp[NC];        // mean over experts
    __shared__ float s_lmp[NC];       // log2(mean + eps)
    __shared__ float red[24];
    __shared__ float s_maxp[NE];
    __shared__ float s_glob[3];       // [sum class var, sum m*l2m, sum m^2]

    const int t    = blockIdx.x;
    const int tid  = threadIdx.x;
    const int lane = tid & 31;
    const int w    = tid >> 5;

    // ---- stage posterior tile (contiguous 32000 B), float4 coalesced ----
    {
        const float4* src = (const float4*)(post + (size_t)t * (NE * NC));
        float4* dst = (float4*)tile;
        #pragma unroll
        for (int i = tid; i < (NE * NC) / 4; i += 256) dst[i] = src[i];
    }
    __syncthreads();

    // ---- pass A (one-shot, vectorized): thread tid<250 owns classes 4t..4t+3
    float a_var = 0.0f, a_ment = 0.0f, a_mn2 = 0.0f;
    if (tid < 250) {
        float p[8][4];
        #pragma unroll
        for (int e = 0; e < 8; e++) {
            float4 v = ((const float4*)tile)[e * 250 + tid];
            p[e][0] = v.x; p[e][1] = v.y; p[e][2] = v.z; p[e][3] = v.w;
        }
        float m[4], lm[4];
        #pragma unroll
        for (int j = 0; j < 4; j++) {
            float s = 0.0f, ss = 0.0f;
            #pragma unroll
            for (int e = 0; e < 8; e++) {
                s += p[e][j];
                ss = fmaf(p[e][j], p[e][j], ss);
            }
            float mj = s * 0.125f;
            m[j] = mj;
            lm[j] = __log2f(mj + 1e-8f);
            a_var  += (ss - 8.0f * mj * mj) * (1.0f / 7.0f);
            a_ment  = fmaf(mj, lm[j], a_ment);
            a_mn2   = fmaf(mj, mj, a_mn2);
        }
        float4 m4;  m4.x = m[0];  m4.y = m[1];  m4.z = m[2];  m4.w = m[3];
        float4 l4;  l4.x = lm[0]; l4.y = lm[1]; l4.z = lm[2]; l4.w = lm[3];
        ((float4*)s_mp)[tid]  = m4;
        ((float4*)s_lmp)[tid] = l4;
    }
    a_var  = warp_sum(a_var);
    a_ment = warp_sum(a_ment);
    a_mn2  = warp_sum(a_mn2);
    if (lane == 0) { red[w] = a_var; red[8 + w] = a_ment; red[16 + w] = a_mn2; }
    __syncthreads();
    if (tid == 0) {
        float v = 0.0f, me = 0.0f, mn2 = 0.0f;
        #pragma unroll
        for (int i = 0; i < 8; i++) { v += red[i]; me += red[8 + i]; mn2 += red[16 + i]; }
        s_glob[0] = v; s_glob[1] = me; s_glob[2] = mn2;
    }
    __syncthreads();

    // ---- pass B: warp w handles expert e = w, float4 per iteration ----
    {
        const int e = w;
        float s_plp = 0.0f, n2 = 0.0f, dot = 0.0f, klb = 0.0f;   // log2 domain
        float t0 = -1e30f, t1 = -1e30f, t2 = -1e30f, t3 = -1e30f, t4 = -1e30f;

        const float4* prow = (const float4*)(tile + e * NC);
        const float4* mrow = (const float4*)s_mp;
        const float4* lrow = (const float4*)s_lmp;

        for (int q = lane; q < 250; q += 32) {
            float4 pv = prow[q];
            float4 mv = mrow[q];
            float4 lv = lrow[q];
            #pragma unroll
            for (int j = 0; j < 4; j++) {
                float pp = (j == 0) ? pv.x : (j == 1) ? pv.y : (j == 2) ? pv.z : pv.w;
                float mm = (j == 0) ? mv.x : (j == 1) ? mv.y : (j == 2) ? mv.z : mv.w;
                float ll = (j == 0) ? lv.x : (j == 1) ? lv.y : (j == 2) ? lv.z : lv.w;
                float lp = __log2f(pp + 1e-8f);
                s_plp = fmaf(pp, lp, s_plp);
                n2    = fmaf(pp, pp, n2);
                dot   = fmaf(pp, mm, dot);
                klb   = fmaf(pp, ll, klb);
                // branchless sorted top-5 insert (9 FMNMX)
                float c1 = fminf(t0, pp); t0 = fmaxf(t0, pp);
                float c2 = fminf(t1, c1); t1 = fmaxf(t1, c1);
                float c3 = fminf(t2, c2); t2 = fmaxf(t2, c2);
                float c4 = fminf(t3, c3); t3 = fmaxf(t3, c3);
                t4 = fmaxf(t4, c4);
            }
        }
        s_plp = warp_sum(s_plp);
        n2    = warp_sum(n2);
        dot   = warp_sum(dot);
        klb   = warp_sum(klb);

        // merge lane-local top-5 lists: 5 rounds of warp argmax, winner pops
        int k = 0;
        float tkl[5];
        #pragma unroll
        for (int r = 0; r < 5; r++) {
            float cand = (k == 0) ? t0 : (k == 1) ? t1 : (k == 2) ? t2
                       : (k == 3) ? t3 : (k == 4) ? t4 : -1e30f;
            float best = cand;
            int bl = lane;
            #pragma unroll
            for (int o = 16; o; o >>= 1) {
                float ov = __shfl_xor_sync(0xffffffffu, best, o);
                int   ol = __shfl_xor_sync(0xffffffffu, bl, o);
                if (ov > best || (ov == best && ol < bl)) { best = ov; bl = ol; }
            }
            tkl[r] = best;
            if (lane == bl) k++;
        }

        if (lane == 0) {
            float tk0 = tkl[0], tk1 = tkl[1];
            float mass = tkl[0] + tkl[1] + tkl[2] + tkl[3] + tkl[4];
            float ent  = -LN2F * s_plp;
            float kl   = LN2F * (s_plp - klb);
            float pn   = fmaxf(sqrtf(n2), 1e-8f);
            float mn   = fmaxf(sqrtf(s_glob[2]), 1e-8f);
            float cosv = dot / (pn * mn);
            float* fr = outFeats + (size_t)t * DFEAT;
            fr[0 * 8 + e] = clipf(ent);
            fr[1 * 8 + e] = clipf(mass);
            fr[2 * 8 + e] = clipf(1.0f - mass);
            fr[3 * 8 + e] = clipf(tk0);
            fr[4 * 8 + e] = clipf(tk0 - tk1);
            fr[5 * 8 + e] = clipf(cosv);
            fr[6 * 8 + e] = clipf(kl);
            s_maxp[e] = tk0;
        }
    }
    __syncthreads();

    if (tid == 0) {
        float s = 0.0f;
        #pragma unroll
        for (int e = 0; e < NE; e++) s += s_maxp[e];
        float mean = s * 0.125f;
        float ss = 0.0f;
        #pragma unroll
        for (int e = 0; e < NE; e++) { float d = s_maxp[e] - mean; ss = fmaf(d, d, ss); }
        float stdm = sqrtf(ss * (1.0f / 7.0f));   // ddof=1
        float* fr = outFeats + (size_t)t * DFEAT;
        fr[56] = clipf(-LN2F * s_glob[1]);        // mean entropy
        fr[57] = clipf(s_glob[0] * (1.0f / NC));  // mean class var
        fr[58] = clipf(stdm);                     // std of max probs
    }
}

// ---------------------------------------------------------------------------
// Kernel 2: feats(59) @ W1 -> LN -> ReLU -> g_h1 (32 tokens / block)
// ---------------------------------------------------------------------------
__global__ __launch_bounds__(256) void mlp1_kernel(
    const float* __restrict__ feats,
    const float* __restrict__ W1, const float* __restrict__ b1,
    const float* __restrict__ g1, const float* __restrict__ be1)
{
    __shared__ float sf[32 * 60];    // feats tile, padded stride 60
    __shared__ float sh[32 * 260];   // h1 tile for LN, stride 260

    const int t0  = blockIdx.x * 32;
    const int tid = threadIdx.x;
    const int lane = tid & 31;
    const int tg   = tid >> 5;
    const int j0   = lane * 8;

    {
        const float* src = feats + (size_t)t0 * DFEAT;
        for (int i = tid; i < 32 * DFEAT; i += 256) {
            int tt = i / DFEAT, d = i - tt * DFEAT;
            sf[tt * 60 + d] = src[i];
        }
    }
    __syncthreads();

    float acc[4][8];
    #pragma unroll
    for (int a = 0; a < 4; a++)
        #pragma unroll
        for (int b = 0; b < 8; b++) acc[a][b] = 0.0f;

    #pragma unroll 2
    for (int k = 0; k < DFEAT; k++) {
        float4 wa = *(const float4*)(W1 + k * NH1 + j0);
        float4 wb = *(const float4*)(W1 + k * NH1 + j0 + 4);
        float wv[8] = {wa.x, wa.y, wa.z, wa.w, wb.x, wb.y, wb.z, wb.w};
        #pragma unroll
        for (int a = 0; a < 4; a++) {
            float f = sf[(tg * 4 + a) * 60 + k];
            #pragma unroll
            for (int b = 0; b < 8; b++) acc[a][b] = fmaf(f, wv[b], acc[a][b]);
        }
    }

    float4 ba = *(const float4*)(b1 + j0);
    float4 bb = *(const float4*)(b1 + j0 + 4);
    float bv[8] = {ba.x, ba.y, ba.z, ba.w, bb.x, bb.y, bb.z, bb.w};
    #pragma unroll
    for (int a = 0; a < 4; a++)
        #pragma unroll
        for (int b = 0; b < 8; b++)
            sh[(tg * 4 + a) * 260 + j0 + b] = acc[a][b] + bv[b];
    __syncthreads();

    // LN + ReLU: warp tg handles tokens tg*4 .. tg*4+3
    #pragma unroll
    for (int a = 0; a < 4; a++) {
        int tt = tg * 4 + a;
        float s = 0.0f;
        #pragma unroll
        for (int j = lane; j < NH1; j += 32) s += sh[tt * 260 + j];
        s = warp_sum(s);
        float mu = s * (1.0f / NH1);
        float vs = 0.0f;
        #pragma unroll
        for (int j = lane; j < NH1; j += 32) {
            float d = sh[tt * 260 + j] - mu;
            vs = fmaf(d, d, vs);
        }
        vs = warp_sum(vs);
        float inv = rsqrtf(vs * (1.0f / NH1) + 1e-5f);
        float* dst = g_h1 + (size_t)(t0 + tt) * NH1;
        #pragma unroll
        for (int j = lane; j < NH1; j += 32) {
            float x = (sh[tt * 260 + j] - mu) * inv * g1[j] + be1[j];
            dst[j] = fmaxf(x, 0.0f);
        }
    }
}

// ---------------------------------------------------------------------------
// Kernel 3: g_h1(256) @ W2 -> LN -> ReLU -> g_h2 (32 tokens / block)
// ---------------------------------------------------------------------------
__global__ __launch_bounds__(256) void mlp2_kernel(
    const float* __restrict__ W2, const float* __restrict__ b2,
    const float* __restrict__ g2, const float* __restrict__ be2)
{
    __shared__ float sh1[32 * 256];  // 32 KB; reused for h2 (32*132) after GEMM

    const int t0  = blockIdx.x * 32;
    const int tid = threadIdx.x;
    const int lane = tid & 31;
    const int tg   = tid >> 5;
    const int j0   = lane * 4;

    {
        const float4* src = (const float4*)(g_h1 + (size_t)t0 * NH1);
        float4* dst = (float4*)sh1;
        #pragma unroll
        for (int i = tid; i < (32 * NH1) / 4; i += 256) dst[i] = src[i];
    }
    __syncthreads();

    float acc[4][4];
    #pragma unroll
    for (int a = 0; a < 4; a++)
        #pragma unroll
        for (int b = 0; b < 4; b++) acc[a][b] = 0.0f;

    #pragma unroll 4
    for (int k = 0; k < NH1; k++) {
        float4 w4 = *(const float4*)(W2 + k * NH2 + j0);
        float wv[4] = {w4.x, w4.y, w4.z, w4.w};
        #pragma unroll
        for (int a = 0; a < 4; a++) {
            float f = sh1[(tg * 4 + a) * NH1 + k];
            #pragma unroll
            for (int b = 0; b < 4; b++) acc[a][b] = fmaf(f, wv[b], acc[a][b]);
        }
    }
    __syncthreads();   // everyone done reading sh1 before reuse

    float4 b4 = *(const float4*)(b2 + j0);
    float bv[4] = {b4.x, b4.y, b4.z, b4.w};
    float* sh2 = sh1;  // reuse, stride 132
    #pragma unroll
    for (int a = 0; a < 4; a++)
        #pragma unroll
        for (int b = 0; b < 4; b++)
            sh2[(tg * 4 + a) * 132 + j0 + b] = acc[a][b] + bv[b];
    __syncthreads();

    #pragma unroll
    for (int a = 0; a < 4; a++) {
        int tt = tg * 4 + a;
        float s = 0.0f;
        #pragma unroll
        for (int j = lane; j < NH2; j += 32) s += sh2[tt * 132 + j];
        s = warp_sum(s);
        float mu = s * (1.0f / NH2);
        float vs = 0.0f;
        #pragma unroll
        for (int j = lane; j < NH2; j += 32) {
            float d = sh2[tt * 132 + j] - mu;
            vs = fmaf(d, d, vs);
        }
        vs = warp_sum(vs);
        float inv = rsqrtf(vs * (1.0f / NH2) + 1e-5f);
        float* dst = g_h2 + (size_t)(t0 + tt) * NH2;
        #pragma unroll
        for (int j = lane; j < NH2; j += 32) {
            float x = (sh2[tt * 132 + j] - mu) * inv * g2[j] + be2[j];
            dst[j] = fmaxf(x, 0.0f);
        }
    }
}

// ---------------------------------------------------------------------------
// Kernel 4: g_h2(128) @ W3 + b3 -> logits; softmax -> weights.
// Thread-per-token; W3 staged in SMEM (uniform-address broadcast LDS).
// ---------------------------------------------------------------------------
__global__ __launch_bounds__(256) void mlp3_kernel(
    const float* __restrict__ W3, const float* __restrict__ b3,
    float* __restrict__ weights, float* __restrict__ logits, int B)
{
    __shared__ float sW[NH2 * 8];
    __shared__ float sb[8];
    for (int i = threadIdx.x; i < NH2 * 8; i += 256) sW[i] = W3[i];
    if (threadIdx.x < 8) sb[threadIdx.x] = b3[threadIdx.x];
    __syncthreads();

    const int t = blockIdx.x * 256 + threadIdx.x;
    if (t >= B) return;

    const float4* h4 = (const float4*)(g_h2 + (size_t)t * NH2);
    float acc[8];
    #pragma unroll
    for (int e = 0; e < 8; e++) acc[e] = 0.0f;

    #pragma unroll
    for (int k4 = 0; k4 < NH2 / 4; k4++) {
        float4 hv = h4[k4];
        const float* wr = sW + k4 * 32;
        #pragma unroll
        for (int e = 0; e < 8; e++) {
            acc[e] = fmaf(hv.x, wr[0 * 8 + e], acc[e]);
            acc[e] = fmaf(hv.y, wr[1 * 8 + e], acc[e]);
            acc[e] = fmaf(hv.z, wr[2 * 8 + e], acc[e]);
            acc[e] = fmaf(hv.w, wr[3 * 8 + e], acc[e]);
        }
    }

    float lg[8];
    float mx = -1e30f;
    #pragma unroll
    for (int e = 0; e < 8; e++) { lg[e] = acc[e] + sb[e]; mx = fmaxf(mx, lg[e]); }
    float ex[8];
    float s = 0.0f;
    #pragma unroll
    for (int e = 0; e < 8; e++) { ex[e] = __expf(lg[e] - mx); s += ex[e]; }
    float inv = 1.0f / s;

    float4* lgo = (float4*)(logits + (size_t)t * 8);
    float4* wgo = (float4*)(weights + (size_t)t * 8);
    float4 v;
    v.x = lg[0]; v.y = lg[1]; v.z = lg[2]; v.w = lg[3]; lgo[0] = v;
    v.x = lg[4]; v.y = lg[5]; v.z = lg[6]; v.w = lg[7]; lgo[1] = v;
    v.x = ex[0] * inv; v.y = ex[1] * inv; v.z = ex[2] * inv; v.w = ex[3] * inv; wgo[0] = v;
    v.x = ex[4] * inv; v.y = ex[5] * inv; v.z = ex[6] * inv; v.w = ex[7] * inv; wgo[1] = v;
}

// ---------------------------------------------------------------------------
extern "C" void kernel_launch(void* const* d_in, const int* in_sizes, int n_in,
                              void* d_out, int out_size)
{
    const float* post = (const float*)d_in[0];
    const float* W1   = (const float*)d_in[1];
    const float* b1   = (const float*)d_in[2];
    const float* g1   = (const float*)d_in[3];
    const float* be1  = (const float*)d_in[4];
    const float* W2   = (const float*)d_in[5];
    const float* b2   = (const float*)d_in[6];
    const float* g2   = (const float*)d_in[7];
    const float* be2  = (const float*)d_in[8];
    const float* W3   = (const float*)d_in[9];
    const float* b3   = (const float*)d_in[10];

    const int B = in_sizes[0] / (NE * NC);

    float* out     = (float*)d_out;
    float* weights = out;                       // (B, 8)
    float* logits  = out + (size_t)B * 8;       // (B, 8)
    float* feats   = out + (size_t)B * 16;      // (B, 59)

    feat_kernel<<<B, 256>>>(post, feats);
    mlp1_kernel<<<B / 32, 256>>>(feats, W1, b1, g1, be1);
    mlp2_kernel<<<B / 32, 256>>>(W2, b2, g2, be2);
    mlp3_kernel<<<(B + 255) / 256, 256>>>(W3, b3, weights, logits, B);
}

// round 9
// speedup vs baseline: 1.4738x; 1.4738x over previous
#include <cuda_runtime.h>
#include <math.h>

#define NE 8
#define NC 1000
#define DFEAT 59
#define NH1 256
#define NH2 128
#define MAXB 16384
#define LN2F 0.69314718055994530942f

// scratch (no allocations allowed)
__device__ float g_h1[(size_t)MAXB * NH1];
__device__ float g_h2[(size_t)MAXB * NH2];

__device__ __forceinline__ float clipf(float x) {
    return fminf(fmaxf(x, -100.0f), 100.0f);
}

__device__ __forceinline__ float warp_sum(float v) {
    #pragma unroll
    for (int o = 16; o; o >>= 1) v += __shfl_xor_sync(0xffffffffu, v, o);
    return v;
}

// ---------------------------------------------------------------------------
// Kernel 1: feature extraction. One block per token (256 threads = 8 warps).
// Logs on MUFU (LG2), accumulate in log2 domain, scale by ln2 at the end.
// ---------------------------------------------------------------------------
__global__ __launch_bounds__(256) void feat_kernel(
    const float* __restrict__ post, float* __restrict__ outFeats)
{
    __shared__ float tile[NE * NC];   // 32 KB
    __shared__ float s_mp[NC];        // mean over experts
    __shared__ float s_lmp[NC];       // log2(mean + eps)
    __shared__ float red[24];
    __shared__ float s_maxp[NE];
    __shared__ float s_glob[3];       // [sum class var, sum m*l2m, sum m^2]

    const int t    = blockIdx.x;
    const int tid  = threadIdx.x;
    const int lane = tid & 31;
    const int w    = tid >> 5;

    // ---- stage posterior tile (contiguous 32000 B), float4 coalesced ----
    {
        const float4* src = (const float4*)(post + (size_t)t * (NE * NC));
        float4* dst = (float4*)tile;
        #pragma unroll
        for (int i = tid; i < (NE * NC) / 4; i += 256) dst[i] = src[i];
    }
    __syncthreads();

    // ---- pass A (one-shot, vectorized): thread tid<250 owns classes 4t..4t+3
    float a_var = 0.0f, a_ment = 0.0f, a_mn2 = 0.0f;
    if (tid < 250) {
        float p[8][4];
        #pragma unroll
        for (int e = 0; e < 8; e++) {
            float4 v = ((const float4*)tile)[e * 250 + tid];
            p[e][0] = v.x; p[e][1] = v.y; p[e][2] = v.z; p[e][3] = v.w;
        }
        float m[4], lm[4];
        #pragma unroll
        for (int j = 0; j < 4; j++) {
            float s = 0.0f, ss = 0.0f;
            #pragma unroll
            for (int e = 0; e < 8; e++) {
                s += p[e][j];
                ss = fmaf(p[e][j], p[e][j], ss);
            }
            float mj = s * 0.125f;
            m[j] = mj;
            lm[j] = __log2f(mj + 1e-8f);
            a_var  += (ss - 8.0f * mj * mj) * (1.0f / 7.0f);
            a_ment  = fmaf(mj, lm[j], a_ment);
            a_mn2   = fmaf(mj, mj, a_mn2);
        }
        float4 m4;  m4.x = m[0];  m4.y = m[1];  m4.z = m[2];  m4.w = m[3];
        float4 l4;  l4.x = lm[0]; l4.y = lm[1]; l4.z = lm[2]; l4.w = lm[3];
        ((float4*)s_mp)[tid]  = m4;
        ((float4*)s_lmp)[tid] = l4;
    }
    a_var  = warp_sum(a_var);
    a_ment = warp_sum(a_ment);
    a_mn2  = warp_sum(a_mn2);
    if (lane == 0) { red[w] = a_var; red[8 + w] = a_ment; red[16 + w] = a_mn2; }
    __syncthreads();
    if (tid == 0) {
        float v = 0.0f, me = 0.0f, mn2 = 0.0f;
        #pragma unroll
        for (int i = 0; i < 8; i++) { v += red[i]; me += red[8 + i]; mn2 += red[16 + i]; }
        s_glob[0] = v; s_glob[1] = me; s_glob[2] = mn2;
    }
    __syncthreads();

    // ---- pass B: warp w handles expert e = w, float4 per iteration ----
    {
        const int e = w;
        float s_plp = 0.0f, n2 = 0.0f, dot = 0.0f, klb = 0.0f;   // log2 domain
        float t0 = -1e30f, t1 = -1e30f, t2 = -1e30f, t3 = -1e30f, t4 = -1e30f;

        const float4* prow = (const float4*)(tile + e * NC);
        const float4* mrow = (const float4*)s_mp;
        const float4* lrow = (const float4*)s_lmp;

        for (int q = lane; q < 250; q += 32) {
            float4 pv = prow[q];
            float4 mv = mrow[q];
            float4 lv = lrow[q];
            #pragma unroll
            for (int j = 0; j < 4; j++) {
                float pp = (j == 0) ? pv.x : (j == 1) ? pv.y : (j == 2) ? pv.z : pv.w;
                float mm = (j == 0) ? mv.x : (j == 1) ? mv.y : (j == 2) ? mv.z : mv.w;
                float ll = (j == 0) ? lv.x : (j == 1) ? lv.y : (j == 2) ? lv.z : lv.w;
                float lp = __log2f(pp + 1e-8f);
                s_plp = fmaf(pp, lp, s_plp);
                n2    = fmaf(pp, pp, n2);
                dot   = fmaf(pp, mm, dot);
                klb   = fmaf(pp, ll, klb);
                // branchless sorted top-5 insert (9 FMNMX)
                float c1 = fminf(t0, pp); t0 = fmaxf(t0, pp);
                float c2 = fminf(t1, c1); t1 = fmaxf(t1, c1);
                float c3 = fminf(t2, c2); t2 = fmaxf(t2, c2);
                float c4 = fminf(t3, c3); t3 = fmaxf(t3, c3);
                t4 = fmaxf(t4, c4);
            }
        }
        s_plp = warp_sum(s_plp);
        n2    = warp_sum(n2);
        dot   = warp_sum(dot);
        klb   = warp_sum(klb);

        // merge lane-local top-5 lists: 5 rounds of warp argmax, winner pops
        int k = 0;
        float tkl[5];
        #pragma unroll
        for (int r = 0; r < 5; r++) {
            float cand = (k == 0) ? t0 : (k == 1) ? t1 : (k == 2) ? t2
                       : (k == 3) ? t3 : (k == 4) ? t4 : -1e30f;
            float best = cand;
            int bl = lane;
            #pragma unroll
            for (int o = 16; o; o >>= 1) {
                float ov = __shfl_xor_sync(0xffffffffu, best, o);
                int   ol = __shfl_xor_sync(0xffffffffu, bl, o);
                if (ov > best || (ov == best && ol < bl)) { best = ov; bl = ol; }
            }
            tkl[r] = best;
            if (lane == bl) k++;
        }

        if (lane == 0) {
            float tk0 = tkl[0], tk1 = tkl[1];
            float mass = tkl[0] + tkl[1] + tkl[2] + tkl[3] + tkl[4];
            float ent  = -LN2F * s_plp;
            float kl   = LN2F * (s_plp - klb);
            float pn   = fmaxf(sqrtf(n2), 1e-8f);
            float mn   = fmaxf(sqrtf(s_glob[2]), 1e-8f);
            float cosv = dot / (pn * mn);
            float* fr = outFeats + (size_t)t * DFEAT;
            fr[0 * 8 + e] = clipf(ent);
            fr[1 * 8 + e] = clipf(mass);
            fr[2 * 8 + e] = clipf(1.0f - mass);
            fr[3 * 8 + e] = clipf(tk0);
            fr[4 * 8 + e] = clipf(tk0 - tk1);
            fr[5 * 8 + e] = clipf(cosv);
            fr[6 * 8 + e] = clipf(kl);
            s_maxp[e] = tk0;
        }
    }
    __syncthreads();

    if (tid == 0) {
        float s = 0.0f;
        #pragma unroll
        for (int e = 0; e < NE; e++) s += s_maxp[e];
        float mean = s * 0.125f;
        float ss = 0.0f;
        #pragma unroll
        for (int e = 0; e < NE; e++) { float d = s_maxp[e] - mean; ss = fmaf(d, d, ss); }
        float stdm = sqrtf(ss * (1.0f / 7.0f));   // ddof=1
        float* fr = outFeats + (size_t)t * DFEAT;
        fr[56] = clipf(-LN2F * s_glob[1]);        // mean entropy
        fr[57] = clipf(s_glob[0] * (1.0f / NC));  // mean class var
        fr[58] = clipf(stdm);                     // std of max probs
    }
}

// ---------------------------------------------------------------------------
// Kernel 2: feats(59) @ W1 -> LN -> ReLU -> g_h1 (32 tokens / block)
// ---------------------------------------------------------------------------
__global__ __launch_bounds__(256) void mlp1_kernel(
    const float* __restrict__ feats,
    const float* __restrict__ W1, const float* __restrict__ b1,
    const float* __restrict__ g1, const float* __restrict__ be1)
{
    __shared__ float sf[32 * 60];    // feats tile, padded stride 60
    __shared__ float sh[32 * 260];   // h1 tile for LN, stride 260

    const int t0  = blockIdx.x * 32;
    const int tid = threadIdx.x;
    const int lane = tid & 31;
    const int tg   = tid >> 5;
    const int j0   = lane * 8;

    {
        const float* src = feats + (size_t)t0 * DFEAT;
        for (int i = tid; i < 32 * DFEAT; i += 256) {
            int tt = i / DFEAT, d = i - tt * DFEAT;
            sf[tt * 60 + d] = src[i];
        }
    }
    __syncthreads();

    float acc[4][8];
    #pragma unroll
    for (int a = 0; a < 4; a++)
        #pragma unroll
        for (int b = 0; b < 8; b++) acc[a][b] = 0.0f;

    #pragma unroll 2
    for (int k = 0; k < DFEAT; k++) {
        float4 wa = *(const float4*)(W1 + k * NH1 + j0);
        float4 wb = *(const float4*)(W1 + k * NH1 + j0 + 4);
        float wv[8] = {wa.x, wa.y, wa.z, wa.w, wb.x, wb.y, wb.z, wb.w};
        #pragma unroll
        for (int a = 0; a < 4; a++) {
            float f = sf[(tg * 4 + a) * 60 + k];
            #pragma unroll
            for (int b = 0; b < 8; b++) acc[a][b] = fmaf(f, wv[b], acc[a][b]);
        }
    }

    float4 ba = *(const float4*)(b1 + j0);
    float4 bb = *(const float4*)(b1 + j0 + 4);
    float bv[8] = {ba.x, ba.y, ba.z, ba.w, bb.x, bb.y, bb.z, bb.w};
    #pragma unroll
    for (int a = 0; a < 4; a++)
        #pragma unroll
        for (int b = 0; b < 8; b++)
            sh[(tg * 4 + a) * 260 + j0 + b] = acc[a][b] + bv[b];
    __syncthreads();

    // LN + ReLU: warp tg handles tokens tg*4 .. tg*4+3
    #pragma unroll
    for (int a = 0; a < 4; a++) {
        int tt = tg * 4 + a;
        float s = 0.0f;
        #pragma unroll
        for (int j = lane; j < NH1; j += 32) s += sh[tt * 260 + j];
        s = warp_sum(s);
        float mu = s * (1.0f / NH1);
        float vs = 0.0f;
        #pragma unroll
        for (int j = lane; j < NH1; j += 32) {
            float d = sh[tt * 260 + j] - mu;
            vs = fmaf(d, d, vs);
        }
        vs = warp_sum(vs);
        float inv = rsqrtf(vs * (1.0f / NH1) + 1e-5f);
        float* dst = g_h1 + (size_t)(t0 + tt) * NH1;
        #pragma unroll
        for (int j = lane; j < NH1; j += 32) {
            float x = (sh[tt * 260 + j] - mu) * inv * g1[j] + be1[j];
            dst[j] = fmaxf(x, 0.0f);
        }
    }
}

// ---------------------------------------------------------------------------
// Kernel 3: g_h1(256) @ W2 -> LN -> ReLU -> g_h2 (32 tokens / block)
// ---------------------------------------------------------------------------
__global__ __launch_bounds__(256) void mlp2_kernel(
    const float* __restrict__ W2, const float* __restrict__ b2,
    const float* __restrict__ g2, const float* __restrict__ be2)
{
    __shared__ float sh1[32 * 256];  // 32 KB; reused for h2 (32*132) after GEMM

    const int t0  = blockIdx.x * 32;
    const int tid = threadIdx.x;
    const int lane = tid & 31;
    const int tg   = tid >> 5;
    const int j0   = lane * 4;

    {
        const float4* src = (const float4*)(g_h1 + (size_t)t0 * NH1);
        float4* dst = (float4*)sh1;
        #pragma unroll
        for (int i = tid; i < (32 * NH1) / 4; i += 256) dst[i] = src[i];
    }
    __syncthreads();

    float acc[4][4];
    #pragma unroll
    for (int a = 0; a < 4; a++)
        #pragma unroll
        for (int b = 0; b < 4; b++) acc[a][b] = 0.0f;

    #pragma unroll 4
    for (int k = 0; k < NH1; k++) {
        float4 w4 = *(const float4*)(W2 + k * NH2 + j0);
        float wv[4] = {w4.x, w4.y, w4.z, w4.w};
        #pragma unroll
        for (int a = 0; a < 4; a++) {
            float f = sh1[(tg * 4 + a) * NH1 + k];
            #pragma unroll
            for (int b = 0; b < 4; b++) acc[a][b] = fmaf(f, wv[b], acc[a][b]);
        }
    }
    __syncthreads();   // everyone done reading sh1 before reuse

    float4 b4 = *(const float4*)(b2 + j0);
    float bv[4] = {b4.x, b4.y, b4.z, b4.w};
    float* sh2 = sh1;  // reuse, stride 132
    #pragma unroll
    for (int a = 0; a < 4; a++)
        #pragma unroll
        for (int b = 0; b < 4; b++)
            sh2[(tg * 4 + a) * 132 + j0 + b] = acc[a][b] + bv[b];
    __syncthreads();

    #pragma unroll
    for (int a = 0; a < 4; a++) {
        int tt = tg * 4 + a;
        float s = 0.0f;
        #pragma unroll
        for (int j = lane; j < NH2; j += 32) s += sh2[tt * 132 + j];
        s = warp_sum(s);
        float mu = s * (1.0f / NH2);
        float vs = 0.0f;
        #pragma unroll
        for (int j = lane; j < NH2; j += 32) {
            float d = sh2[tt * 132 + j] - mu;
            vs = fmaf(d, d, vs);
        }
        vs = warp_sum(vs);
        float inv = rsqrtf(vs * (1.0f / NH2) + 1e-5f);
        float* dst = g_h2 + (size_t)(t0 + tt) * NH2;
        #pragma unroll
        for (int j = lane; j < NH2; j += 32) {
            float x = (sh2[tt * 132 + j] - mu) * inv * g2[j] + be2[j];
            dst[j] = fmaxf(x, 0.0f);
        }
    }
}

// ---------------------------------------------------------------------------
// Kernel 4: g_h2(128) @ W3 + b3 -> logits; softmax -> weights.
// Thread-per-token; W3 staged in SMEM (uniform-address broadcast LDS).
// ---------------------------------------------------------------------------
__global__ __launch_bounds__(256) void mlp3_kernel(
    const float* __restrict__ W3, const float* __restrict__ b3,
    float* __restrict__ weights, float* __restrict__ logits, int B)
{
    __shared__ float sW[NH2 * 8];
    __shared__ float sb[8];
    for (int i = threadIdx.x; i < NH2 * 8; i += 256) sW[i] = W3[i];
    if (threadIdx.x < 8) sb[threadIdx.x] = b3[threadIdx.x];
    __syncthreads();

    const int t = blockIdx.x * 256 + threadIdx.x;
    if (t >= B) return;

    const float4* h4 = (const float4*)(g_h2 + (size_t)t * NH2);
    float acc[8];
    #pragma unroll
    for (int e = 0; e < 8; e++) acc[e] = 0.0f;

    #pragma unroll
    for (int k4 = 0; k4 < NH2 / 4; k4++) {
        float4 hv = h4[k4];
        const float* wr = sW + k4 * 32;
        #pragma unroll
        for (int e = 0; e < 8; e++) {
            acc[e] = fmaf(hv.x, wr[0 * 8 + e], acc[e]);
            acc[e] = fmaf(hv.y, wr[1 * 8 + e], acc[e]);
            acc[e] = fmaf(hv.z, wr[2 * 8 + e], acc[e]);
            acc[e] = fmaf(hv.w, wr[3 * 8 + e], acc[e]);
        }
    }

    float lg[8];
    float mx = -1e30f;
    #pragma unroll
    for (int e = 0; e < 8; e++) { lg[e] = acc[e] + sb[e]; mx = fmaxf(mx, lg[e]); }
    float ex[8];
    float s = 0.0f;
    #pragma unroll
    for (int e = 0; e < 8; e++) { ex[e] = __expf(lg[e] - mx); s += ex[e]; }
    float inv = 1.0f / s;

    float4* lgo = (float4*)(logits + (size_t)t * 8);
    float4* wgo = (float4*)(weights + (size_t)t * 8);
    float4 v;
    v.x = lg[0]; v.y = lg[1]; v.z = lg[2]; v.w = lg[3]; lgo[0] = v;
    v.x = lg[4]; v.y = lg[5]; v.z = lg[6]; v.w = lg[7]; lgo[1] = v;
    v.x = ex[0] * inv; v.y = ex[1] * inv; v.z = ex[2] * inv; v.w = ex[3] * inv; wgo[0] = v;
    v.x = ex[4] * inv; v.y = ex[5] * inv; v.z = ex[6] * inv; v.w = ex[7] * inv; wgo[1] = v;
}

// ---------------------------------------------------------------------------
extern "C" void kernel_launch(void* const* d_in, const int* in_sizes, int n_in,
                              void* d_out, int out_size)
{
    const float* post = (const float*)d_in[0];
    const float* W1   = (const float*)d_in[1];
    const float* b1   = (const float*)d_in[2];
    const float* g1   = (const float*)d_in[3];
    const float* be1  = (const float*)d_in[4];
    const float* W2   = (const float*)d_in[5];
    const float* b2   = (const float*)d_in[6];
    const float* g2   = (const float*)d_in[7];
    const float* be2  = (const float*)d_in[8];
    const float* W3   = (const float*)d_in[9];
    const float* b3   = (const float*)d_in[10];

    const int B = in_sizes[0] / (NE * NC);

    float* out     = (float*)d_out;
    float* weights = out;                       // (B, 8)
    float* logits  = out + (size_t)B * 8;       // (B, 8)
    float* feats   = out + (size_t)B * 16;      // (B, 59)

    feat_kernel<<<B, 256>>>(post, feats);
    mlp1_kernel<<<B / 32, 256>>>(feats, W1, b1, g1, be1);
    mlp2_kernel<<<B / 32, 256>>>(W2, b2, g2, be2);
    mlp3_kernel<<<(B + 255) / 256, 256>>>(W3, b3, weights, logits, B);
}

// round 10
// speedup vs baseline: 1.8312x; 1.2425x over previous
#include <cuda_runtime.h>
#include <math.h>

#define NE 8
#define NC 1000
#define DFEAT 59
#define NH1 256
#define NH2 128
#define LN2F 0.69314718055994530942f

__device__ __forceinline__ float clipf(float x) {
    return fminf(fmaxf(x, -100.0f), 100.0f);
}

__device__ __forceinline__ float warp_sum(float v) {
    #pragma unroll
    for (int o = 16; o; o >>= 1) v += __shfl_xor_sync(0xffffffffu, v, o);
    return v;
}

// packed f32x2 FMA (Blackwell): acc.lo += a.lo*b.lo; acc.hi += a.hi*b.hi
__device__ __forceinline__ void ffma2(unsigned long long& acc,
                                      unsigned long long a, unsigned long long b) {
    asm("fma.rn.f32x2 %0, %1, %2, %0;" : "+l"(acc) : "l"(a), "l"(b));
}
__device__ __forceinline__ unsigned long long pack2(float lo, float hi) {
    unsigned long long r;
    asm("mov.b64 %0, {%1, %2};" : "=l"(r) : "f"(lo), "f"(hi));
    return r;
}
__device__ __forceinline__ float2 unpack2(unsigned long long v) {
    float2 r;
    asm("mov.b64 {%0, %1}, %2;" : "=f"(r.x), "=f"(r.y) : "l"(v));
    return r;
}

union F4U2 { float4 f; ulonglong2 u; };

// ---------------------------------------------------------------------------
// Kernel 1: feature extraction. One block per token, 256 threads (8 warps).
// No SMEM tile: pass A and pass B both read GMEM (pass B hits L1/L2).
// ---------------------------------------------------------------------------
__global__ __launch_bounds__(256) void feat_kernel(
    const float* __restrict__ post, float* __restrict__ outFeats)
{
    __shared__ __align__(16) float s_mp[1024];   // mean over experts (+pad)
    __shared__ __align__(16) float s_lmp[1024];  // log2(mean+eps)    (+pad)
    __shared__ float red[24];
    __shared__ float s_maxp[NE];
    __shared__ float s_glob[3];  // [sum class var, sum m*l2m, sum m^2]

    const int t    = blockIdx.x;
    const int tid  = threadIdx.x;
    const int lane = tid & 31;
    const int w    = tid >> 5;

    const float4* base = (const float4*)(post + (size_t)t * (NE * NC)); // 2000 float4

    // ---- pass A: thread tid<250 owns classes 4*tid..4*tid+3, all 8 experts ----
    float a_var = 0.0f, a_ment = 0.0f, a_mn2 = 0.0f;
    if (tid < 250) {
        float4 v = base[tid];
        float sx = v.x, sy = v.y, sz = v.z, sw = v.w;
        float qx = v.x * v.x, qy = v.y * v.y, qz = v.z * v.z, qw = v.w * v.w;
        #pragma unroll
        for (int e = 1; e < 8; e++) {
            v = base[e * 250 + tid];
            sx += v.x; sy += v.y; sz += v.z; sw += v.w;
            qx = fmaf(v.x, v.x, qx); qy = fmaf(v.y, v.y, qy);
            qz = fmaf(v.z, v.z, qz); qw = fmaf(v.w, v.w, qw);
        }
        float m[4] = {sx * 0.125f, sy * 0.125f, sz * 0.125f, sw * 0.125f};
        float q[4] = {qx, qy, qz, qw};
        float lm[4];
        #pragma unroll
        for (int j = 0; j < 4; j++) {
            lm[j] = __log2f(m[j] + 1e-8f);
            a_var += fmaf(-8.0f * m[j], m[j], q[j]) * (1.0f / 7.0f);
            a_ment = fmaf(m[j], lm[j], a_ment);
            a_mn2  = fmaf(m[j], m[j], a_mn2);
        }
        float4 m4; m4.x = m[0];  m4.y = m[1];  m4.z = m[2];  m4.w = m[3];
        float4 l4; l4.x = lm[0]; l4.y = lm[1]; l4.z = lm[2]; l4.w = lm[3];
        ((float4*)s_mp)[tid]  = m4;
        ((float4*)s_lmp)[tid] = l4;
    } else {
        // zero the pad slots (250..255) so pass-B OOB lanes read clean zeros
        float4 z = make_float4(0.f, 0.f, 0.f, 0.f);
        ((float4*)s_mp)[tid]  = z;
        ((float4*)s_lmp)[tid] = z;
    }
    a_var  = warp_sum(a_var);
    a_ment = warp_sum(a_ment);
    a_mn2  = warp_sum(a_mn2);
    if (lane == 0) { red[w] = a_var; red[8 + w] = a_ment; red[16 + w] = a_mn2; }
    __syncthreads();
    if (tid == 0) {
        float v = 0.0f, me = 0.0f, mn2 = 0.0f;
        #pragma unroll
        for (int i = 0; i < 8; i++) { v += red[i]; me += red[8 + i]; mn2 += red[16 + i]; }
        s_glob[0] = v; s_glob[1] = me; s_glob[2] = mn2;
    }
    __syncthreads();

    // ---- pass B: warp w = expert w; GMEM re-read (L1/L2 hit) ----
    {
        const int e = w;
        const float4* prow = base + e * 250;
        unsigned long long splp = 0ull, an2 = 0ull, adot = 0ull, aklb = 0ull;
        float t_0 = -1e30f, t_1 = -1e30f, t_2 = -1e30f, t_3 = -1e30f, t_4 = -1e30f;

        #pragma unroll
        for (int k = 0; k < 8; k++) {
            const int q = lane + 32 * k;
            F4U2 pv;
            if (q < 250) pv.f = __ldg(prow + q);
            else         pv.f = make_float4(0.f, 0.f, 0.f, 0.f);
            F4U2 mv, lv;
            mv.u = ((const ulonglong2*)s_mp)[q];    // pads are zero
            lv.u = ((const ulonglong2*)s_lmp)[q];

            float lp0 = __log2f(pv.f.x + 1e-8f);
            float lp1 = __log2f(pv.f.y + 1e-8f);
            float lp2 = __log2f(pv.f.z + 1e-8f);
            float lp3 = __log2f(pv.f.w + 1e-8f);
            unsigned long long lp01 = pack2(lp0, lp1);
            unsigned long long lp23 = pack2(lp2, lp3);

            ffma2(splp, pv.u.x, lp01);  ffma2(splp, pv.u.y, lp23);
            ffma2(an2,  pv.u.x, pv.u.x); ffma2(an2,  pv.u.y, pv.u.y);
            ffma2(adot, pv.u.x, mv.u.x); ffma2(adot, pv.u.y, mv.u.y);
            ffma2(aklb, pv.u.x, lv.u.x); ffma2(aklb, pv.u.y, lv.u.y);

            // branchless sorted top-5 insert, 9 FMNMX per scalar
            #define TOP5_INS(P) { \
                float c1 = fminf(t_0, (P)); t_0 = fmaxf(t_0, (P)); \
                float c2 = fminf(t_1, c1);  t_1 = fmaxf(t_1, c1); \
                float c3 = fminf(t_2, c2);  t_2 = fmaxf(t_2, c2); \
                float c4 = fminf(t_3, c3);  t_3 = fmaxf(t_3, c3); \
                t_4 = fmaxf(t_4, c4); }
            TOP5_INS(pv.f.x) TOP5_INS(pv.f.y) TOP5_INS(pv.f.z) TOP5_INS(pv.f.w)
            #undef TOP5_INS
        }

        float2 u;
        u = unpack2(splp); float s_plp = u.x + u.y;
        u = unpack2(an2);  float n2    = u.x + u.y;
        u = unpack2(adot); float dot   = u.x + u.y;
        u = unpack2(aklb); float klb   = u.x + u.y;
        s_plp = warp_sum(s_plp);
        n2    = warp_sum(n2);
        dot   = warp_sum(dot);
        klb   = warp_sum(klb);

        // merge lane-local top-5: 5 rounds of warp argmax, winner pops
        int k = 0;
        float tkl[5];
        #pragma unroll
        for (int r = 0; r < 5; r++) {
            float cand = (k == 0) ? t_0 : (k == 1) ? t_1 : (k == 2) ? t_2
                       : (k == 3) ? t_3 : (k == 4) ? t_4 : -1e30f;
            float best = cand;
            int bl = lane;
            #pragma unroll
            for (int o = 16; o; o >>= 1) {
                float ov = __shfl_xor_sync(0xffffffffu, best, o);
                int   ol = __shfl_xor_sync(0xffffffffu, bl, o);
                if (ov > best || (ov == best && ol < bl)) { best = ov; bl = ol; }
            }
            tkl[r] = best;
            if (lane == bl) k++;
        }

        if (lane == 0) {
            float tk0 = tkl[0], tk1 = tkl[1];
            float mass = tkl[0] + tkl[1] + tkl[2] + tkl[3] + tkl[4];
            float ent  = -LN2F * s_plp;
            float kl   = LN2F * (s_plp - klb);
            float pn   = fmaxf(sqrtf(n2), 1e-8f);
            float mn   = fmaxf(sqrtf(s_glob[2]), 1e-8f);
            float cosv = dot / (pn * mn);
            float* fr = outFeats + (size_t)t * DFEAT;
            fr[0 * 8 + e] = clipf(ent);
            fr[1 * 8 + e] = clipf(mass);
            fr[2 * 8 + e] = clipf(1.0f - mass);
            fr[3 * 8 + e] = clipf(tk0);
            fr[4 * 8 + e] = clipf(tk0 - tk1);
            fr[5 * 8 + e] = clipf(cosv);
            fr[6 * 8 + e] = clipf(kl);
            s_maxp[e] = tk0;
        }
    }
    __syncthreads();

    if (tid == 0) {
        float s = 0.0f;
        #pragma unroll
        for (int e = 0; e < NE; e++) s += s_maxp[e];
        float mean = s * 0.125f;
        float ss = 0.0f;
        #pragma unroll
        for (int e = 0; e < NE; e++) { float d = s_maxp[e] - mean; ss = fmaf(d, d, ss); }
        float stdm = sqrtf(ss * (1.0f / 7.0f));   // ddof=1
        float* fr = outFeats + (size_t)t * DFEAT;
        fr[56] = clipf(-LN2F * s_glob[1]);        // mean entropy
        fr[57] = clipf(s_glob[0] * (1.0f / NC));  // mean class var
        fr[58] = clipf(stdm);                     // std of max probs
    }
}

// ---------------------------------------------------------------------------
// Kernel 2: fused MLP. 32 tokens per block, 256 threads.
// feats -> (GEMM1 + LN + ReLU) -> (GEMM2 + LN + ReLU) -> (GEMM3 + softmax).
// h1, h2 never leave shared memory.
// ---------------------------------------------------------------------------
__global__ __launch_bounds__(256) void mlp_fused(
    const float* __restrict__ feats,
    const float* __restrict__ W1, const float* __restrict__ b1,
    const float* __restrict__ g1, const float* __restrict__ be1,
    const float* __restrict__ W2, const float* __restrict__ b2,
    const float* __restrict__ g2, const float* __restrict__ be2,
    const float* __restrict__ W3, const float* __restrict__ b3,
    float* __restrict__ weights, float* __restrict__ logits)
{
    __shared__ float sf[32 * 60];     // feats, padded stride 60
    __shared__ float sh[32 * 260];    // h1 (pre-LN, then LN+ReLU in place)
    __shared__ float sh2[32 * 132];   // h2 (pre-LN, then LN+ReLU in place)
    __shared__ float sW3[8 * NH2];    // W3 transposed: [e][k]
    __shared__ float sb3[8];

    const int t0   = blockIdx.x * 32;
    const int tid  = threadIdx.x;
    const int lane = tid & 31;
    const int tg   = tid >> 5;

    // stage feats + W3(transposed) + b3
    {
        const float* src = feats + (size_t)t0 * DFEAT;
        for (int i = tid; i < 32 * DFEAT; i += 256) {
            int tt = i / DFEAT, d = i - tt * DFEAT;
            sf[tt * 60 + d] = src[i];
        }
        for (int i = tid; i < NH2 * 8; i += 256) {
            int k = i >> 3, e = i & 7;
            sW3[e * NH2 + k] = W3[i];
        }
        if (tid < 8) sb3[tid] = b3[tid];
    }
    __syncthreads();

    // ---- GEMM1: 4 tokens x 8 cols per thread ----
    {
        const int j0 = lane * 8;
        float acc[4][8];
        #pragma unroll
        for (int a = 0; a < 4; a++)
            #pragma unroll
            for (int b = 0; b < 8; b++) acc[a][b] = 0.0f;

        #pragma unroll 2
        for (int k = 0; k < DFEAT; k++) {
            float4 wa = *(const float4*)(W1 + k * NH1 + j0);
            float4 wb = *(const float4*)(W1 + k * NH1 + j0 + 4);
            float wv[8] = {wa.x, wa.y, wa.z, wa.w, wb.x, wb.y, wb.z, wb.w};
            #pragma unroll
            for (int a = 0; a < 4; a++) {
                float f = sf[(tg * 4 + a) * 60 + k];
                #pragma unroll
                for (int b = 0; b < 8; b++) acc[a][b] = fmaf(f, wv[b], acc[a][b]);
            }
        }
        float4 ba = *(const float4*)(b1 + j0);
        float4 bb = *(const float4*)(b1 + j0 + 4);
        float bv[8] = {ba.x, ba.y, ba.z, ba.w, bb.x, bb.y, bb.z, bb.w};
        #pragma unroll
        for (int a = 0; a < 4; a++)
            #pragma unroll
            for (int b = 0; b < 8; b++)
                sh[(tg * 4 + a) * 260 + j0 + b] = acc[a][b] + bv[b];
    }
    __syncthreads();

    // ---- LN1 + ReLU (in place) ----
    #pragma unroll
    for (int a = 0; a < 4; a++) {
        int tt = tg * 4 + a;
        float s = 0.0f;
        #pragma unroll
        for (int j = lane; j < NH1; j += 32) s += sh[tt * 260 + j];
        s = warp_sum(s);
        float mu = s * (1.0f / NH1);
        float vs = 0.0f;
        #pragma unroll
        for (int j = lane; j < NH1; j += 32) {
            float d = sh[tt * 260 + j] - mu;
            vs = fmaf(d, d, vs);
        }
        vs = warp_sum(vs);
        float inv = rsqrtf(vs * (1.0f / NH1) + 1e-5f);
        #pragma unroll
        for (int j = lane; j < NH1; j += 32) {
            float x = (sh[tt * 260 + j] - mu) * inv * g1[j] + be1[j];
            sh[tt * 260 + j] = fmaxf(x, 0.0f);
        }
    }
    __syncthreads();

    // ---- GEMM2: 4 tokens x 4 cols per thread ----
    {
        const int j0 = lane * 4;
        float acc[4][4];
        #pragma unroll
        for (int a = 0; a < 4; a++)
            #pragma unroll
            for (int b = 0; b < 4; b++) acc[a][b] = 0.0f;

        #pragma unroll 4
        for (int k = 0; k < NH1; k++) {
            float4 w4 = *(const float4*)(W2 + k * NH2 + j0);
            float wv[4] = {w4.x, w4.y, w4.z, w4.w};
            #pragma unroll
            for (int a = 0; a < 4; a++) {
                float f = sh[(tg * 4 + a) * 260 + k];
                #pragma unroll
                for (int b = 0; b < 4; b++) acc[a][b] = fmaf(f, wv[b], acc[a][b]);
            }
        }
        float4 b4 = *(const float4*)(b2 + j0);
        float bv[4] = {b4.x, b4.y, b4.z, b4.w};
        #pragma unroll
        for (int a = 0; a < 4; a++)
            #pragma unroll
            for (int b = 0; b < 4; b++)
                sh2[(tg * 4 + a) * 132 + j0 + b] = acc[a][b] + bv[b];
    }
    __syncthreads();

    // ---- LN2 + ReLU (in place) ----
    #pragma unroll
    for (int a = 0; a < 4; a++) {
        int tt = tg * 4 + a;
        float s = 0.0f;
        #pragma unroll
        for (int j = lane; j < NH2; j += 32) s += sh2[tt * 132 + j];
        s = warp_sum(s);
        float mu = s * (1.0f / NH2);
        float vs = 0.0f;
        #pragma unroll
        for (int j = lane; j < NH2; j += 32) {
            float d = sh2[tt * 132 + j] - mu;
            vs = fmaf(d, d, vs);
        }
        vs = warp_sum(vs);
        float inv = rsqrtf(vs * (1.0f / NH2) + 1e-5f);
        #pragma unroll
        for (int j = lane; j < NH2; j += 32) {
            float x = (sh2[tt * 132 + j] - mu) * inv * g2[j] + be2[j];
            sh2[tt * 132 + j] = fmaxf(x, 0.0f);
        }
    }
    __syncwarp();  // warp tg consumes only its own 4 tokens below

    // ---- GEMM3 + softmax: warp tg handles tokens tg*4..tg*4+3 ----
    #pragma unroll
    for (int a = 0; a < 4; a++) {
        int tt = tg * 4 + a;
        const float* h = &sh2[tt * 132];
        float acc[8];
        #pragma unroll
        for (int e = 0; e < 8; e++) acc[e] = 0.0f;
        #pragma unroll
        for (int i = 0; i < 4; i++) {
            int k = lane + 32 * i;
            float f = h[k];
            #pragma unroll
            for (int e = 0; e < 8; e++) acc[e] = fmaf(f, sW3[e * NH2 + k], acc[e]);
        }
        #pragma unroll
        for (int e = 0; e < 8; e++) acc[e] = warp_sum(acc[e]);

        if (lane == 0) {
            int t = t0 + tt;
            float lg[8];
            float mx = -1e30f;
            #pragma unroll
            for (int e = 0; e < 8; e++) { lg[e] = acc[e] + sb3[e]; mx = fmaxf(mx, lg[e]); }
            float ex[8];
            float s = 0.0f;
            #pragma unroll
            for (int e = 0; e < 8; e++) { ex[e] = __expf(lg[e] - mx); s += ex[e]; }
            float inv = 1.0f / s;
            float4* lgo = (float4*)(logits + (size_t)t * 8);
            float4* wgo = (float4*)(weights + (size_t)t * 8);
            float4 v;
            v.x = lg[0]; v.y = lg[1]; v.z = lg[2]; v.w = lg[3]; lgo[0] = v;
            v.x = lg[4]; v.y = lg[5]; v.z = lg[6]; v.w = lg[7]; lgo[1] = v;
            v.x = ex[0] * inv; v.y = ex[1] * inv; v.z = ex[2] * inv; v.w = ex[3] * inv; wgo[0] = v;
            v.x = ex[4] * inv; v.y = ex[5] * inv; v.z = ex[6] * inv; v.w = ex[7] * inv; wgo[1] = v;
        }
    }
}

// ---------------------------------------------------------------------------
extern "C" void kernel_launch(void* const* d_in, const int* in_sizes, int n_in,
                              void* d_out, int out_size)
{
    const float* post = (const float*)d_in[0];
    const float* W1   = (const float*)d_in[1];
    const float* b1   = (const float*)d_in[2];
    const float* g1   = (const float*)d_in[3];
    const float* be1  = (const float*)d_in[4];
    const float* W2   = (const float*)d_in[5];
    const float* b2   = (const float*)d_in[6];
    const float* g2   = (const float*)d_in[7];
    const float* be2  = (const float*)d_in[8];
    const float* W3   = (const float*)d_in[9];
    const float* b3   = (const float*)d_in[10];

    const int B = in_sizes[0] / (NE * NC);

    float* out     = (float*)d_out;
    float* weights = out;                       // (B, 8)
    float* logits  = out + (size_t)B * 8;       // (B, 8)
    float* feats   = out + (size_t)B * 16;      // (B, 59)

    feat_kernel<<<B, 256>>>(post, feats);
    mlp_fused<<<B / 32, 256>>>(feats, W1, b1, g1, be1, W2, b2, g2, be2,
                               W3, b3, weights, logits);
}